// round 9
// baseline (speedup 1.0000x reference)
#include <cuda_runtime.h>

#define IMGW    2048
#define NPATCH  65536
#define NNODES  255
#define NINT    127
#define KK      64
#define DEPTH   7
#define NLEAF   128
#define WSTRIDE 66           // W row stride; halves at +0 / +33
#define XSTRIDE 65           // patch-spill row stride (2-way conflicts max)
#define NBLK    128          // k_descent blocks

__device__ float g_S[NLEAF * KK];
__device__ float g_cnt[NLEAF];
__device__ float g_part[NBLK * NLEAF * KK];   // per-block partial sums (4MB)
__device__ float g_pcnt[NBLK * NLEAF];        // per-block partial counts

// ---------------------------------------------------------------------------
// K1: fused prep + descent + per-block bucket sums. 128 blocks x 512 threads.
// Two lanes per patch (parity split of the 64-dim dot), two patches per
// thread (pA, pB = pA + 32768). After descent, patch pixels are spilled to
// shared and 4 threads/leaf accumulate this block's patches in fixed slot
// order (deterministic), emitting partial sums to g_part.
// ---------------------------------------------------------------------------
// smem layout: sleaf[512 B] | W[8384 f] | sT[128 f] | shx[512*65 f]
#define SMEM1 (512 + 8384 * 4 + 128 * 4 + 512 * XSTRIDE * 4)

__global__ __launch_bounds__(512) void k_descent(const float* __restrict__ image,
                                                 const float* __restrict__ nodes,
                                                 float* __restrict__ out_cur)
{
    extern __shared__ char smem[];
    unsigned char* sleaf = reinterpret_cast<unsigned char*>(smem);
    float* W   = reinterpret_cast<float*>(smem + 512);
    float* sT  = W + 8384;
    float* shx = sT + 128;

    const int tid    = threadIdx.x;
    const int lane   = tid & 31;
    const int wid    = tid >> 5;
    const int parity = tid & 1;

    // ---- hoisted patch loads (fill LDG scoreboard before prologue) ----
    const int pA  = blockIdx.x * 256 + (tid >> 1);   // 0..32767
    const int pB  = pA + 32768;
    const int piA = pA >> 8, pjA = pA & 255;
    const int piB = pB >> 8, pjB = pB & 255;
    const float* baseA = image + (piA * 8 + parity * 4) * IMGW + pjA * 8;
    const float* baseB = image + (piB * 8 + parity * 4) * IMGW + pjB * 8;

    float xA[32], xB[32];
#pragma unroll
    for (int r = 0; r < 4; ++r) {
        float4 a0 = *reinterpret_cast<const float4*>(baseA + r * IMGW);
        float4 a1 = *reinterpret_cast<const float4*>(baseA + r * IMGW + 4);
        float4 b0 = *reinterpret_cast<const float4*>(baseB + r * IMGW);
        float4 b1 = *reinterpret_cast<const float4*>(baseB + r * IMGW + 4);
        xA[r*8+0]=a0.x; xA[r*8+1]=a0.y; xA[r*8+2]=a0.z; xA[r*8+3]=a0.w;
        xA[r*8+4]=a1.x; xA[r*8+5]=a1.y; xA[r*8+6]=a1.z; xA[r*8+7]=a1.w;
        xB[r*8+0]=b0.x; xB[r*8+1]=b0.y; xB[r*8+2]=b0.z; xB[r*8+3]=b0.w;
        xB[r*8+4]=b1.x; xB[r*8+5]=b1.y; xB[r*8+6]=b1.z; xB[r*8+7]=b1.w;
    }

    // ---- prologue: W pass (coalesced). element k of node i -> halves ----
    for (int e = tid; e < NINT * KK; e += 512) {
        const int i = e >> 6, k = e & 63;
        const float a = nodes[128 * i + 64 + k];
        const float b = nodes[128 * i + 128 + k];
        W[i * WSTRIDE + (k & 31) + (k >> 5) * 33] = a - b;
    }
    // ---- prologue: T pass (warp-per-node butterfly, canonical pairing) ----
    for (int i = wid; i < NINT; i += 16) {
        const float a0 = nodes[128 * i + 64 + lane];
        const float b0 = nodes[128 * i + 128 + lane];
        const float a1 = nodes[128 * i + 96 + lane];
        const float b1 = nodes[128 * i + 160 + lane];
        float r = (a0 * a0 - b0 * b0) + (a1 * a1 - b1 * b1);
#pragma unroll
        for (int off = 16; off > 0; off >>= 1)
            r += __shfl_xor_sync(0xFFFFFFFFu, r, off);
        if (lane == 0) sT[i] = 0.5f * r;
    }
    __syncthreads();

    const float* wbase = W + parity * 33;
    int curA = 0, curB = 0;
#pragma unroll 1
    for (int lvl = 0; lvl < DEPTH; ++lvl) {
        const float* wA = wbase + curA * WSTRIDE;
        const float* wB = wbase + curB * WSTRIDE;
        float a0 = 0.f, a1 = 0.f, a2 = 0.f, a3 = 0.f;
        float b0 = 0.f, b1 = 0.f, b2 = 0.f, b3 = 0.f;
#pragma unroll
        for (int k = 0; k < 32; k += 4) {
            a0 = fmaf(xA[k + 0], wA[k + 0], a0);
            b0 = fmaf(xB[k + 0], wB[k + 0], b0);
            a1 = fmaf(xA[k + 1], wA[k + 1], a1);
            b1 = fmaf(xB[k + 1], wB[k + 1], b1);
            a2 = fmaf(xA[k + 2], wA[k + 2], a2);
            b2 = fmaf(xB[k + 2], wB[k + 2], b2);
            a3 = fmaf(xA[k + 3], wA[k + 3], a3);
            b3 = fmaf(xB[k + 3], wB[k + 3], b3);
        }
        const float mineA  = (a0 + a1) + (a2 + a3);
        const float mineB  = (b0 + b1) + (b2 + b3);
        const float otherA = __shfl_xor_sync(0xFFFFFFFFu, mineA, 1);
        const float otherB = __shfl_xor_sync(0xFFFFFFFFu, mineB, 1);
        const float hA0 = parity ? otherA : mineA;
        const float hA1 = parity ? mineA  : otherA;
        const float hB0 = parity ? otherB : mineB;
        const float hB1 = parity ? mineB  : otherB;
        const float dotA = hA0 + hA1;        // identical on both pair lanes
        const float dotB = hB0 + hB1;
        curA = 2 * curA + 1 + ((dotA < sT[curA]) ? 1 : 0);
        curB = 2 * curB + 1 + ((dotB < sT[curB]) ? 1 : 0);
    }
    if (parity == 0) {
        out_cur[pA] = (float)curA;
        out_cur[pB] = (float)curB;
    }

    // ---- epilogue: spill patches to shared, per-leaf block-local sums ----
    const int sA = tid >> 1;                 // slot 0..255
    const int sB = 256 + (tid >> 1);         // slot 256..511
#pragma unroll
    for (int i = 0; i < 32; ++i) {
        shx[sA * XSTRIDE + parity * 32 + i] = xA[i];
        shx[sB * XSTRIDE + parity * 32 + i] = xB[i];
    }
    if (parity == 0) {
        sleaf[sA] = (unsigned char)(curA - 127);
        sleaf[sB] = (unsigned char)(curB - 127);
    }
    __syncthreads();

    const int leaf = tid >> 2;               // 0..127
    const int k0   = (tid & 3) * 16;
    const unsigned lvb = (unsigned)leaf * 0x01010101u;
    const uint4* su4 = reinterpret_cast<const uint4*>(sleaf);

    float acc[16];
#pragma unroll
    for (int i = 0; i < 16; ++i) acc[i] = 0.f;
    int cnt = 0;

#pragma unroll 1
    for (int w = 0; w < 32; ++w) {
        const uint4 u = su4[w];
#pragma unroll
        for (int word = 0; word < 4; ++word) {
            const unsigned uw = (word == 0) ? u.x : (word == 1) ? u.y
                              : (word == 2) ? u.z : u.w;
            unsigned m = __vcmpeq4(uw, lvb);
            while (m) {
                const int byte = (__ffs(m) - 1) >> 3;
                const int slot = w * 16 + word * 4 + byte;
                const float* xp = shx + slot * XSTRIDE + k0;
#pragma unroll
                for (int i = 0; i < 16; ++i) acc[i] += xp[i];
                ++cnt;
                m &= ~(0xFFu << (byte * 8));
            }
        }
    }

    float* dst = g_part + (blockIdx.x * NLEAF + leaf) * KK + k0;
#pragma unroll
    for (int i = 0; i < 16; i += 4)
        *reinterpret_cast<float4*>(dst + i) = make_float4(acc[i], acc[i+1], acc[i+2], acc[i+3]);
    if ((tid & 3) == 0)
        g_pcnt[blockIdx.x * NLEAF + leaf] = (float)cnt;
}

// ---------------------------------------------------------------------------
// K2: fold 128 block-partials into g_S / g_cnt. 128 blocks (leaf) x 64 (k).
// Fixed strided-accumulator order -> deterministic.
// ---------------------------------------------------------------------------
__global__ __launch_bounds__(64) void k_reduce()
{
    const int leaf = blockIdx.x;
    const int k    = threadIdx.x;
    float a0 = 0.f, a1 = 0.f, a2 = 0.f, a3 = 0.f;
#pragma unroll 4
    for (int b = 0; b < NBLK; b += 4) {
        a0 += g_part[((b + 0) * NLEAF + leaf) * KK + k];
        a1 += g_part[((b + 1) * NLEAF + leaf) * KK + k];
        a2 += g_part[((b + 2) * NLEAF + leaf) * KK + k];
        a3 += g_part[((b + 3) * NLEAF + leaf) * KK + k];
    }
    g_S[leaf * KK + k] = (a0 + a1) + (a2 + a3);

    if (k < 32) {
        float c = ((g_pcnt[(4 * k + 0) * NLEAF + leaf]
                  + g_pcnt[(4 * k + 1) * NLEAF + leaf])
                  + g_pcnt[(4 * k + 2) * NLEAF + leaf])
                  + g_pcnt[(4 * k + 3) * NLEAF + leaf];
#pragma unroll
        for (int off = 16; off > 0; off >>= 1)
            c += __shfl_xor_sync(0xFFFFFFFFu, c, off);
        if (k == 0) g_cnt[leaf] = c;
    }
}

// ---------------------------------------------------------------------------
// K3: fused subtree-tree + node update. 128 blocks x 512 threads (wide grid).
// Each block redundantly builds H (subtree sums of S) + counts in shared,
// then emits 2 node rows via telescoped ancestor sums:
//   sum_l lrate[min(lv,cp)]*S[l,:] = lr0*H[root] + sum_t lrate[t-1]*H[anc_t]
// ---------------------------------------------------------------------------
#define SMEM3 ((NNODES * KK + NNODES + 1) * 4)

__global__ __launch_bounds__(512) void k_final(const float* __restrict__ nodes,
                                               float* __restrict__ out_nodes)
{
    extern __shared__ float shH[];               // [NNODES*KK]
    float* shC = shH + NNODES * KK;              // [NNODES]
    const int tid = threadIdx.x;

    // leaves: nodes 127..254
    for (int i = tid; i < NLEAF * KK; i += 512)
        shH[(NINT << 6) + i] = g_S[i];
    if (tid < NLEAF)
        shC[NINT + tid] = g_cnt[tid];
    __syncthreads();

    // upward passes
#pragma unroll
    for (int lvl = DEPTH - 1; lvl >= 0; --lvl) {
        const int first = (1 << lvl) - 1;
        const int n     = 1 << lvl;              // nodes at this level
        for (int e = tid; e < n * KK; e += 512) {
            const int i = first + (e >> 6);
            const int k = e & 63;
            shH[i * KK + k] = shH[(2 * i + 1) * KK + k] + shH[(2 * i + 2) * KK + k];
        }
        if (tid < n) {
            const int i = first + tid;
            shC[i] = shC[2 * i + 1] + shC[2 * i + 2];
        }
        __syncthreads();
    }

    // this block emits node rows 2b and 2b+1
    const int g = tid >> 6;            // 0..7
    const int k = tid & 63;
    if (g >= 2) return;
    const int j = blockIdx.x * 2 + g;
    if (j >= NNODES) return;
    const float nv = nodes[j * 64 + k];
    if (j == 0) {                      // root is not updated
        out_nodes[k] = nv;
        return;
    }
    const int m  = j + 1;              // 1-indexed node in [2,255]
    const int lv = 31 - __clz(m);      // level of node (1..7)

    const float lr0 = 0.3f * __int_as_float(120 << 23);  // 0.3 * 2^-7
    float s1 = lr0 * shH[k];           // root term
    float sc = lr0 * shC[0];
#pragma unroll 1
    for (int t = 1; t <= lv; ++t) {
        const int anc = (m >> (lv - t)) - 1;             // 0-indexed ancestor
        const float lr = 0.3f * __int_as_float((t - 1 + 120) << 23);
        s1 = fmaf(lr, shH[anc * 64 + k], s1);
        sc = fmaf(lr, shC[anc], sc);
    }
    const float invP = 1.0f / 65536.0f;
    out_nodes[j * 64 + k] = nv + s1 * invP - (sc * invP) * nv;
}

// ---------------------------------------------------------------------------
extern "C" void kernel_launch(void* const* d_in, const int* in_sizes, int n_in,
                              void* d_out, int out_size)
{
    const float* image = (const float*)d_in[0];
    const float* nodes = (const float*)d_in[1];
    float* out       = (float*)d_out;
    float* out_nodes = out;                      // 255*64 floats
    float* out_cur   = out + NNODES * KK;        // 65536 floats

    cudaFuncSetAttribute(k_descent, cudaFuncAttributeMaxDynamicSharedMemorySize, SMEM1);
    cudaFuncSetAttribute(k_final,   cudaFuncAttributeMaxDynamicSharedMemorySize, SMEM3);

    k_descent<<<NBLK, 512, SMEM1>>>(image, nodes, out_cur);
    k_reduce<<<NLEAF, 64>>>();
    k_final<<<128, 512, SMEM3>>>(nodes, out_nodes);
}

// round 10
// speedup vs baseline: 1.0548x; 1.0548x over previous
#include <cuda_runtime.h>

#define IMGW    2048
#define NPATCH  65536
#define NNODES  255
#define NINT    127
#define KK      64
#define DEPTH   7
#define NLEAF   128
#define WROW    36           // floats per half-row (8 float4 data + 4 pad)
#define WHALF   (NINT * WROW)   // 4572 floats per parity half

__device__ unsigned char g_leaf[NPATCH];
__device__ float g_part[2 * NLEAF * KK];   // per-half leaf sums
__device__ float g_pcnt[2 * NLEAF];        // per-half leaf counts

// ---------------------------------------------------------------------------
// K1: fused prep + descent. 256 blocks x 512 threads, 2 lanes per patch.
// W stored as two parity-half arrays [127][36] -> float4 LDS (8 LDS.128 per
// level instead of 32 LDS.32). FMA accumulation order identical to prior
// rounds (bit-identical descent decisions). Right iff dot(x,W) < T.
// ---------------------------------------------------------------------------
#define SMEM1 ((2 * WHALF + 128) * 4)

__global__ __launch_bounds__(512) void k_descent(const float* __restrict__ image,
                                                 const float* __restrict__ nodes,
                                                 float* __restrict__ out_cur)
{
    extern __shared__ float sh[];            // W2[2][127][36] | sT[127]
    float* sT = sh + 2 * WHALF;
    const int tid    = threadIdx.x;
    const int lane   = tid & 31;
    const int wid    = tid >> 5;             // 0..15
    const int parity = tid & 1;

    // ---- hoisted patch loads ----
    const int p  = blockIdx.x * 256 + (tid >> 1);   // patch id
    const int pi = p >> 8;
    const int pj = p & 255;
    const float* base = image + (pi * 8 + parity * 4) * IMGW + pj * 8;

    float x[32];
#pragma unroll
    for (int r = 0; r < 4; ++r) {
        float4 v0 = *reinterpret_cast<const float4*>(base + r * IMGW);
        float4 v1 = *reinterpret_cast<const float4*>(base + r * IMGW + 4);
        x[r * 8 + 0] = v0.x; x[r * 8 + 1] = v0.y;
        x[r * 8 + 2] = v0.z; x[r * 8 + 3] = v0.w;
        x[r * 8 + 4] = v1.x; x[r * 8 + 5] = v1.y;
        x[r * 8 + 6] = v1.z; x[r * 8 + 7] = v1.w;
    }

    // ---- prologue: W pass (coalesced) ----
    for (int e = tid; e < NINT * KK; e += 512) {
        const int i = e >> 6, k = e & 63;
        const float a = nodes[128 * i + 64 + k];
        const float b = nodes[128 * i + 128 + k];
        sh[(k >> 5) * WHALF + i * WROW + (k & 31)] = a - b;
    }
    // ---- prologue: T pass (warp-per-node butterfly, canonical pairing) ----
    for (int i = wid; i < NINT; i += 16) {
        const float a0 = nodes[128 * i + 64 + lane];
        const float b0 = nodes[128 * i + 128 + lane];
        const float a1 = nodes[128 * i + 96 + lane];
        const float b1 = nodes[128 * i + 160 + lane];
        float r = (a0 * a0 - b0 * b0) + (a1 * a1 - b1 * b1);
#pragma unroll
        for (int off = 16; off > 0; off >>= 1)
            r += __shfl_xor_sync(0xFFFFFFFFu, r, off);
        if (lane == 0) sT[i] = 0.5f * r;
    }
    __syncthreads();

    const float* wbase = sh + parity * WHALF;
    int cur = 0;
#pragma unroll 1
    for (int lvl = 0; lvl < DEPTH; ++lvl) {
        const float4* wv = reinterpret_cast<const float4*>(wbase + cur * WROW);
        float a0 = 0.f, a1 = 0.f, a2 = 0.f, a3 = 0.f;
#pragma unroll
        for (int j = 0; j < 8; ++j) {
            const float4 v = wv[j];
            a0 = fmaf(x[4 * j + 0], v.x, a0);
            a1 = fmaf(x[4 * j + 1], v.y, a1);
            a2 = fmaf(x[4 * j + 2], v.z, a2);
            a3 = fmaf(x[4 * j + 3], v.w, a3);
        }
        const float mine  = (a0 + a1) + (a2 + a3);
        const float other = __shfl_xor_sync(0xFFFFFFFFu, mine, 1);
        const float h0 = parity ? other : mine;
        const float h1 = parity ? mine  : other;
        const float dot = h0 + h1;           // identical on both pair lanes
        cur = 2 * cur + 1 + ((dot < sT[cur]) ? 1 : 0);
    }
    if (parity == 0) {
        g_leaf[p]  = (unsigned char)(cur - 127);
        out_cur[p] = (float)cur;
    }
}

// ---------------------------------------------------------------------------
// K2: per-(leaf, half) bucket sums, atomic-free & deterministic.
// 256 blocks: block = leaf*2 + half. Each scans its 32K-patch half of
// g_leaf (coalesced uint4, kept in regs for emission), warp-shuffle scan,
// float4 gather (2-way ILP) from the L2-resident image. Partials -> g_part.
// ---------------------------------------------------------------------------
#define HPATCH 32768
#define SMEM2 (HPATCH * 2 + 512 * 16 + 32 * 4 + 16)

__global__ __launch_bounds__(512) void k_bucket(const float* __restrict__ image)
{
    extern __shared__ char smem[];
    unsigned short* list = reinterpret_cast<unsigned short*>(smem);              // 64KB
    float4* red4 = reinterpret_cast<float4*>(smem + HPATCH * 2);                 // 8KB
    int*   wexc  = reinterpret_cast<int*>(smem + HPATCH * 2 + 512 * 16);         // 17 ints

    const int tid  = threadIdx.x;
    const int leaf = blockIdx.x >> 1;
    const int half = blockIdx.x & 1;
    const unsigned lv = (unsigned)leaf * 0x01010101u;
    const uint4* leaf4 = reinterpret_cast<const uint4*>(g_leaf) + half * 2048;

    // coalesced count: 4 uint4 per thread (64B), lanes contiguous
    uint4 v[4];
    int c = 0;
#pragma unroll
    for (int j = 0; j < 4; ++j) {
        v[j] = leaf4[j * 512 + tid];
        c += __popc(__vcmpeq4(v[j].x, lv)) + __popc(__vcmpeq4(v[j].y, lv))
           + __popc(__vcmpeq4(v[j].z, lv)) + __popc(__vcmpeq4(v[j].w, lv));
    }
    c >>= 3;

    // warp-shuffle inclusive scan + cross-warp offsets
    const int lane = tid & 31, wid = tid >> 5;
    int incl = c;
#pragma unroll
    for (int off = 1; off < 32; off <<= 1) {
        int n = __shfl_up_sync(0xFFFFFFFFu, incl, off);
        if (lane >= off) incl += n;
    }
    if (lane == 31) wexc[wid] = incl;
    __syncthreads();
    if (tid < 16) {
        int t = wexc[tid];
        int s = t;
#pragma unroll
        for (int off = 1; off < 16; off <<= 1) {
            int n = __shfl_up_sync(0xFFFFu, s, off);
            if (tid >= off) s += n;
        }
        wexc[tid] = s - t;
        if (tid == 15) wexc[16] = s;
    }
    __syncthreads();
    const int total = wexc[16];
    int pos = wexc[wid] + incl - c;

    // emission from registers (global patch ids; half offset folded in)
    const int pofs = half * HPATCH;
#pragma unroll
    for (int j = 0; j < 4; ++j) {
#pragma unroll
        for (int word = 0; word < 4; ++word) {
            unsigned wv = (word == 0) ? v[j].x : (word == 1) ? v[j].y
                        : (word == 2) ? v[j].z : v[j].w;
            unsigned cmp = __vcmpeq4(wv, lv);
            if (cmp) {
                const int pb = pofs + (j * 512 + tid) * 16 + word * 4;
#pragma unroll
                for (int b = 0; b < 4; ++b)
                    if ((cmp >> (8 * b)) & 1u)
                        list[pos++] = (unsigned short)(pb + b);
            }
        }
    }
    __syncthreads();

    // gather: 32 slots x 16 quads, float4 loads, 2-way ILP, fixed order
    const int q    = tid & 15;
    const int slot = tid >> 4;
    const int r    = q >> 1;
    const int c4   = (q & 1) * 4;
    float4 acc0 = make_float4(0.f, 0.f, 0.f, 0.f);
    float4 acc1 = make_float4(0.f, 0.f, 0.f, 0.f);
    int i = slot;
    for (; i + 32 < total; i += 64) {
        const int p0 = list[i];
        const int p1 = list[i + 32];
        float4 t0 = *reinterpret_cast<const float4*>(
            image + ((p0 >> 8) * 8 + r) * IMGW + (p0 & 255) * 8 + c4);
        float4 t1 = *reinterpret_cast<const float4*>(
            image + ((p1 >> 8) * 8 + r) * IMGW + (p1 & 255) * 8 + c4);
        acc0.x += t0.x; acc0.y += t0.y; acc0.z += t0.z; acc0.w += t0.w;
        acc1.x += t1.x; acc1.y += t1.y; acc1.z += t1.z; acc1.w += t1.w;
    }
    if (i < total) {
        const int p0 = list[i];
        float4 t0 = *reinterpret_cast<const float4*>(
            image + ((p0 >> 8) * 8 + r) * IMGW + (p0 & 255) * 8 + c4);
        acc0.x += t0.x; acc0.y += t0.y; acc0.z += t0.z; acc0.w += t0.w;
    }
    acc0.x += acc1.x; acc0.y += acc1.y; acc0.z += acc1.z; acc0.w += acc1.w;
    red4[tid] = acc0;
    __syncthreads();

    if (tid < 16) {
        float4 s = make_float4(0.f, 0.f, 0.f, 0.f);
#pragma unroll
        for (int sl = 0; sl < 32; ++sl) {
            float4 t = red4[sl * 16 + tid];
            s.x += t.x; s.y += t.y; s.z += t.z; s.w += t.w;
        }
        const int k0 = (tid >> 1) * 8 + (tid & 1) * 4;
        *reinterpret_cast<float4*>(g_part + (half * NLEAF + leaf) * KK + k0) = s;
    }
    if (tid == 0) g_pcnt[half * NLEAF + leaf] = (float)total;
}

// ---------------------------------------------------------------------------
// K3: fused subtree-tree + node update. 128 blocks x 512 threads (wide grid).
// Prologue folds the two bucket halves (fixed order -> deterministic), then
// each block redundantly builds H + counts in shared and emits 2 node rows
// via telescoped ancestor sums:
//   sum_l lrate[min(lv,cp)]*S[l,:] = lr0*H[root] + sum_t lrate[t-1]*H[anc_t]
// ---------------------------------------------------------------------------
#define SMEM3 ((NNODES * KK + NNODES + 1) * 4)

__global__ __launch_bounds__(512) void k_final(const float* __restrict__ nodes,
                                               float* __restrict__ out_nodes)
{
    extern __shared__ float shH[];               // [NNODES*KK]
    float* shC = shH + NNODES * KK;              // [NNODES]
    const int tid = threadIdx.x;

    // leaves: nodes 127..254 (fold halves)
    for (int i = tid; i < NLEAF * KK; i += 512)
        shH[(NINT << 6) + i] = g_part[i] + g_part[NLEAF * KK + i];
    if (tid < NLEAF)
        shC[NINT + tid] = g_pcnt[tid] + g_pcnt[NLEAF + tid];
    __syncthreads();

    // upward passes
#pragma unroll
    for (int lvl = DEPTH - 1; lvl >= 0; --lvl) {
        const int first = (1 << lvl) - 1;
        const int n     = 1 << lvl;
        for (int e = tid; e < n * KK; e += 512) {
            const int i = first + (e >> 6);
            const int k = e & 63;
            shH[i * KK + k] = shH[(2 * i + 1) * KK + k] + shH[(2 * i + 2) * KK + k];
        }
        if (tid < n) {
            const int i = first + tid;
            shC[i] = shC[2 * i + 1] + shC[2 * i + 2];
        }
        __syncthreads();
    }

    // this block emits node rows 2b and 2b+1
    const int g = tid >> 6;            // 0..7
    const int k = tid & 63;
    if (g >= 2) return;
    const int j = blockIdx.x * 2 + g;
    if (j >= NNODES) return;
    const float nv = nodes[j * 64 + k];
    if (j == 0) {                      // root is not updated
        out_nodes[k] = nv;
        return;
    }
    const int m  = j + 1;              // 1-indexed node in [2,255]
    const int lv = 31 - __clz(m);      // level of node (1..7)

    const float lr0 = 0.3f * __int_as_float(120 << 23);  // 0.3 * 2^-7
    float s1 = lr0 * shH[k];           // root term
    float sc = lr0 * shC[0];
#pragma unroll 1
    for (int t = 1; t <= lv; ++t) {
        const int anc = (m >> (lv - t)) - 1;             // 0-indexed ancestor
        const float lr = 0.3f * __int_as_float((t - 1 + 120) << 23);
        s1 = fmaf(lr, shH[anc * 64 + k], s1);
        sc = fmaf(lr, shC[anc], sc);
    }
    const float invP = 1.0f / 65536.0f;
    out_nodes[j * 64 + k] = nv + s1 * invP - (sc * invP) * nv;
}

// ---------------------------------------------------------------------------
extern "C" void kernel_launch(void* const* d_in, const int* in_sizes, int n_in,
                              void* d_out, int out_size)
{
    const float* image = (const float*)d_in[0];
    const float* nodes = (const float*)d_in[1];
    float* out       = (float*)d_out;
    float* out_nodes = out;                      // 255*64 floats
    float* out_cur   = out + NNODES * KK;        // 65536 floats

    cudaFuncSetAttribute(k_descent, cudaFuncAttributeMaxDynamicSharedMemorySize, SMEM1);
    cudaFuncSetAttribute(k_bucket,  cudaFuncAttributeMaxDynamicSharedMemorySize, SMEM2);
    cudaFuncSetAttribute(k_final,   cudaFuncAttributeMaxDynamicSharedMemorySize, SMEM3);

    k_descent<<<NPATCH / 256, 512, SMEM1>>>(image, nodes, out_cur);
    k_bucket<<<2 * NLEAF, 512, SMEM2>>>(image);
    k_final<<<128, 512, SMEM3>>>(nodes, out_nodes);
}

// round 11
// speedup vs baseline: 1.1848x; 1.1232x over previous
#include <cuda_runtime.h>

#define IMGW    2048
#define NPATCH  65536
#define NNODES  255
#define NINT    127
#define KK      64
#define DEPTH   7
#define NLEAF   128
#define WROW    36              // floats per half-row (8 float4 data + 4 pad)
#define WHALF   (NINT * WROW)   // 4572 floats per parity half

__device__ unsigned char g_leaf[NPATCH];
__device__ float g_S[NLEAF * KK];
__device__ float g_cnt[NLEAF];

__device__ __forceinline__ unsigned long long ffma2(unsigned long long a,
                                                    unsigned long long b,
                                                    unsigned long long c)
{
    unsigned long long d;
    asm("fma.rn.f32x2 %0, %1, %2, %3;" : "=l"(d) : "l"(a), "l"(b), "l"(c));
    return d;
}
__device__ __forceinline__ float f2lo(unsigned long long u) { return __uint_as_float((unsigned)u); }
__device__ __forceinline__ float f2hi(unsigned long long u) { return __uint_as_float((unsigned)(u >> 32)); }

// ---------------------------------------------------------------------------
// K1: fused prep + descent. 256 blocks x 512 threads, 2 lanes per patch.
// W as two parity-half arrays [127][36]; rows read as ulonglong2 (LDS.128)
// and consumed by packed fma.rn.f32x2 (16 FFMA2/level instead of 32 FFMA).
// Right iff dot(x,W) < T.
// ---------------------------------------------------------------------------
#define SMEM1 ((2 * WHALF + 128) * 4)

__global__ __launch_bounds__(512) void k_descent(const float* __restrict__ image,
                                                 const float* __restrict__ nodes,
                                                 float* __restrict__ out_cur)
{
    extern __shared__ float sh[];            // W2[2][127][36] | sT[127]
    float* sT = sh + 2 * WHALF;
    const int tid    = threadIdx.x;
    const int lane   = tid & 31;
    const int wid    = tid >> 5;
    const int parity = tid & 1;

    // ---- hoisted patch loads (packed f32x2 pairs) ----
    const int p  = blockIdx.x * 256 + (tid >> 1);
    const int pi = p >> 8;
    const int pj = p & 255;
    const float* base = image + (pi * 8 + parity * 4) * IMGW + pj * 8;

    unsigned long long x2[16];
#pragma unroll
    for (int r = 0; r < 4; ++r) {
        ulonglong2 u0 = *reinterpret_cast<const ulonglong2*>(base + r * IMGW);
        ulonglong2 u1 = *reinterpret_cast<const ulonglong2*>(base + r * IMGW + 4);
        x2[4 * r + 0] = u0.x; x2[4 * r + 1] = u0.y;
        x2[4 * r + 2] = u1.x; x2[4 * r + 3] = u1.y;
    }

    // ---- prologue: W pass (coalesced) ----
    for (int e = tid; e < NINT * KK; e += 512) {
        const int i = e >> 6, k = e & 63;
        const float a = nodes[128 * i + 64 + k];
        const float b = nodes[128 * i + 128 + k];
        sh[(k >> 5) * WHALF + i * WROW + (k & 31)] = a - b;
    }
    // ---- prologue: T pass (warp-per-node butterfly) ----
    for (int i = wid; i < NINT; i += 16) {
        const float a0 = nodes[128 * i + 64 + lane];
        const float b0 = nodes[128 * i + 128 + lane];
        const float a1 = nodes[128 * i + 96 + lane];
        const float b1 = nodes[128 * i + 160 + lane];
        float r = (a0 * a0 - b0 * b0) + (a1 * a1 - b1 * b1);
#pragma unroll
        for (int off = 16; off > 0; off >>= 1)
            r += __shfl_xor_sync(0xFFFFFFFFu, r, off);
        if (lane == 0) sT[i] = 0.5f * r;
    }
    __syncthreads();

    const float* wbase = sh + parity * WHALF;
    int cur = 0;
#pragma unroll 1
    for (int lvl = 0; lvl < DEPTH; ++lvl) {
        const ulonglong2* wv = reinterpret_cast<const ulonglong2*>(wbase + cur * WROW);
        unsigned long long a0 = 0ull, a1 = 0ull, a2 = 0ull, a3 = 0ull;
#pragma unroll
        for (int j = 0; j < 8; j += 2) {
            const ulonglong2 v0 = wv[j];
            const ulonglong2 v1 = wv[j + 1];
            a0 = ffma2(x2[2 * j + 0], v0.x, a0);
            a1 = ffma2(x2[2 * j + 1], v0.y, a1);
            a2 = ffma2(x2[2 * j + 2], v1.x, a2);
            a3 = ffma2(x2[2 * j + 3], v1.y, a3);
        }
        const float mine = ((f2lo(a0) + f2hi(a0)) + (f2lo(a1) + f2hi(a1)))
                         + ((f2lo(a2) + f2hi(a2)) + (f2lo(a3) + f2hi(a3)));
        const float other = __shfl_xor_sync(0xFFFFFFFFu, mine, 1);
        const float h0 = parity ? other : mine;
        const float h1 = parity ? mine  : other;
        const float dot = h0 + h1;           // identical on both pair lanes
        cur = 2 * cur + 1 + ((dot < sT[cur]) ? 1 : 0);
    }
    if (parity == 0) {
        g_leaf[p]  = (unsigned char)(cur - 127);
        out_cur[p] = (float)cur;
    }
}

// ---------------------------------------------------------------------------
// K2: per-leaf bucket sums, atomic-free & deterministic (R7 monolithic form).
// One block per leaf: coalesced uint4 scan of g_leaf (kept in regs for
// emission), warp-shuffle prefix scan, float4 gather (2-way ILP).
// ---------------------------------------------------------------------------
#define SMEM2 (NPATCH * 2 + 512 * 16 + 32 * 4 + 16)

__global__ __launch_bounds__(512) void k_bucket(const float* __restrict__ image)
{
    extern __shared__ char smem[];
    unsigned short* list = reinterpret_cast<unsigned short*>(smem);              // 128KB
    float4* red4 = reinterpret_cast<float4*>(smem + NPATCH * 2);                 // 8KB
    int*   wexc  = reinterpret_cast<int*>(smem + NPATCH * 2 + 512 * 16);         // 17 ints

    const int tid  = threadIdx.x;
    const int leaf = blockIdx.x;
    const unsigned lv = (unsigned)leaf * 0x01010101u;
    const uint4* leaf4 = reinterpret_cast<const uint4*>(g_leaf);

    uint4 v[8];
    int c = 0;
#pragma unroll
    for (int j = 0; j < 8; ++j) {
        v[j] = leaf4[j * 512 + tid];
        c += __popc(__vcmpeq4(v[j].x, lv)) + __popc(__vcmpeq4(v[j].y, lv))
           + __popc(__vcmpeq4(v[j].z, lv)) + __popc(__vcmpeq4(v[j].w, lv));
    }
    c >>= 3;

    const int lane = tid & 31, wid = tid >> 5;
    int incl = c;
#pragma unroll
    for (int off = 1; off < 32; off <<= 1) {
        int n = __shfl_up_sync(0xFFFFFFFFu, incl, off);
        if (lane >= off) incl += n;
    }
    if (lane == 31) wexc[wid] = incl;
    __syncthreads();
    if (tid < 16) {
        int t = wexc[tid];
        int s = t;
#pragma unroll
        for (int off = 1; off < 16; off <<= 1) {
            int n = __shfl_up_sync(0xFFFFu, s, off);
            if (tid >= off) s += n;
        }
        wexc[tid] = s - t;
        if (tid == 15) wexc[16] = s;
    }
    __syncthreads();
    const int total = wexc[16];
    int pos = wexc[wid] + incl - c;

#pragma unroll
    for (int j = 0; j < 8; ++j) {
#pragma unroll
        for (int word = 0; word < 4; ++word) {
            unsigned wv = (word == 0) ? v[j].x : (word == 1) ? v[j].y
                        : (word == 2) ? v[j].z : v[j].w;
            unsigned cmp = __vcmpeq4(wv, lv);
            if (cmp) {
                const int pb = (j * 512 + tid) * 16 + word * 4;
#pragma unroll
                for (int b = 0; b < 4; ++b)
                    if ((cmp >> (8 * b)) & 1u)
                        list[pos++] = (unsigned short)(pb + b);
            }
        }
    }
    __syncthreads();

    const int q    = tid & 15;
    const int slot = tid >> 4;
    const int r    = q >> 1;
    const int c4   = (q & 1) * 4;
    float4 acc0 = make_float4(0.f, 0.f, 0.f, 0.f);
    float4 acc1 = make_float4(0.f, 0.f, 0.f, 0.f);
    int i = slot;
    for (; i + 32 < total; i += 64) {
        const int p0 = list[i];
        const int p1 = list[i + 32];
        float4 t0 = *reinterpret_cast<const float4*>(
            image + ((p0 >> 8) * 8 + r) * IMGW + (p0 & 255) * 8 + c4);
        float4 t1 = *reinterpret_cast<const float4*>(
            image + ((p1 >> 8) * 8 + r) * IMGW + (p1 & 255) * 8 + c4);
        acc0.x += t0.x; acc0.y += t0.y; acc0.z += t0.z; acc0.w += t0.w;
        acc1.x += t1.x; acc1.y += t1.y; acc1.z += t1.z; acc1.w += t1.w;
    }
    if (i < total) {
        const int p0 = list[i];
        float4 t0 = *reinterpret_cast<const float4*>(
            image + ((p0 >> 8) * 8 + r) * IMGW + (p0 & 255) * 8 + c4);
        acc0.x += t0.x; acc0.y += t0.y; acc0.z += t0.z; acc0.w += t0.w;
    }
    acc0.x += acc1.x; acc0.y += acc1.y; acc0.z += acc1.z; acc0.w += acc1.w;
    red4[tid] = acc0;
    __syncthreads();

    if (tid < 16) {
        float4 s = make_float4(0.f, 0.f, 0.f, 0.f);
#pragma unroll
        for (int sl = 0; sl < 32; ++sl) {
            float4 t = red4[sl * 16 + tid];
            s.x += t.x; s.y += t.y; s.z += t.z; s.w += t.w;
        }
        const int k0 = (tid >> 1) * 8 + (tid & 1) * 4;
        *reinterpret_cast<float4*>(g_S + leaf * 64 + k0) = s;
    }
    if (tid == 0) g_cnt[leaf] = (float)total;
}

// ---------------------------------------------------------------------------
// K3: node update, direct clz-coefficient form. 255 blocks x 512 threads.
// 8 groups of 64 threads each partial-sum 16 leaves (fixed order), one smem
// reduce. lr(j,l) = 0.3 * 2^(min(lv, cp(j,l)) - 7).
// ---------------------------------------------------------------------------
__global__ __launch_bounds__(512) void k_update(const float* __restrict__ nodes,
                                                float* __restrict__ out_nodes)
{
    __shared__ float red[8][KK];
    __shared__ float redc[8];
    const int tid = threadIdx.x;
    const int j   = blockIdx.x;          // node row 0..254
    const int k   = tid & 63;
    const int s   = tid >> 6;            // 0..7

    if (j == 0) {                        // root is not updated
        if (tid < KK) out_nodes[tid] = nodes[tid];
        return;
    }
    const int m  = j + 1;                // 1-indexed node in [2,255]
    const int lv = 31 - __clz(m);        // level (1..7)
    const int a  = m << (7 - lv);        // aligned to 8-bit leaf domain

    float s1 = 0.f, sc = 0.f;
#pragma unroll
    for (int i = 0; i < 16; ++i) {
        const int l  = s * 16 + i;
        const int b  = 128 + l;
        const int xr = a ^ b;
        const int mb = xr ? (__clz(xr) - 24) : 8;
        const int state = min(lv, mb - 1);
        const float lr = 0.3f * __int_as_float((state + 120) << 23);
        s1 = fmaf(lr, g_S[l * 64 + k], s1);
        sc = fmaf(lr, g_cnt[l], sc);
    }
    red[s][k] = s1;
    if (k == 0) redc[s] = sc;
    __syncthreads();

    if (tid < KK) {
        const float t1 = ((red[0][tid] + red[1][tid]) + (red[2][tid] + red[3][tid]))
                       + ((red[4][tid] + red[5][tid]) + (red[6][tid] + red[7][tid]));
        const float tc = ((redc[0] + redc[1]) + (redc[2] + redc[3]))
                       + ((redc[4] + redc[5]) + (redc[6] + redc[7]));
        const float invP = 1.0f / 65536.0f;
        const float nv = nodes[j * 64 + tid];
        out_nodes[j * 64 + tid] = nv + t1 * invP - (tc * invP) * nv;
    }
}

// ---------------------------------------------------------------------------
extern "C" void kernel_launch(void* const* d_in, const int* in_sizes, int n_in,
                              void* d_out, int out_size)
{
    const float* image = (const float*)d_in[0];
    const float* nodes = (const float*)d_in[1];
    float* out       = (float*)d_out;
    float* out_nodes = out;                      // 255*64 floats
    float* out_cur   = out + NNODES * KK;        // 65536 floats

    cudaFuncSetAttribute(k_descent, cudaFuncAttributeMaxDynamicSharedMemorySize, SMEM1);
    cudaFuncSetAttribute(k_bucket,  cudaFuncAttributeMaxDynamicSharedMemorySize, SMEM2);

    k_descent<<<NPATCH / 256, 512, SMEM1>>>(image, nodes, out_cur);
    k_bucket<<<NLEAF, 512, SMEM2>>>(image);
    k_update<<<NNODES, 512>>>(nodes, out_nodes);
}